// round 2
// baseline (speedup 1.0000x reference)
#include <cuda_runtime.h>
#include <cuda_bf16.h>
#include <cstdint>

#define NN 100000
#define NE 3200000
#define NG 256

// ---------------- scratch (device globals; no allocation allowed) -------------
__device__ int   g_cnt[NN];
__device__ int   g_rowptr[NN + 1];
__device__ int   g_cursor[NN];
__device__ int   g_col[NE];
__device__ float g_wgt[NE];
__device__ float g_is[NN];                 // inv sqrt degree
__device__ float g_bufA[(size_t)NN * 512];
__device__ float g_bufB[(size_t)NN * 512];
__device__ float g_bufC[(size_t)NN * 1024];
__device__ float g_gsum[NG * 4];
__device__ int   g_gcnt[NG];

// ---------------- small utility kernels ----------------
__global__ void zero_kernel() {
    int i = blockIdx.x * blockDim.x + threadIdx.x;
    if (i < NN) g_cnt[i] = 0;
    if (i < NG * 4) g_gsum[i] = 0.f;
    if (i < NG) g_gcnt[i] = 0;
}

__global__ void hist_kernel(const int* __restrict__ dst) {
    int e = blockIdx.x * blockDim.x + threadIdx.x;
    if (e < NE) atomicAdd(&g_cnt[dst[e]], 1);
}

__global__ void invsqrt_kernel() {
    int i = blockIdx.x * blockDim.x + threadIdx.x;
    if (i < NN) g_is[i] = rsqrtf((float)(g_cnt[i] + 1));   // +1 self loop
}

// single-block exclusive scan of g_cnt -> g_rowptr / g_cursor
__global__ void scan_kernel() {
    __shared__ int sm[1024];
    const int tid = threadIdx.x;
    const int CH = (NN + 1023) / 1024;  // 98
    int base = tid * CH;
    int s = 0;
    for (int i = 0; i < CH; i++) {
        int idx = base + i;
        if (idx < NN) s += g_cnt[idx];
    }
    sm[tid] = s;
    __syncthreads();
    // Hillis-Steele inclusive scan
    for (int off = 1; off < 1024; off <<= 1) {
        int add = (tid >= off) ? sm[tid - off] : 0;
        __syncthreads();
        sm[tid] += add;
        __syncthreads();
    }
    int run = (tid == 0) ? 0 : sm[tid - 1];
    for (int i = 0; i < CH; i++) {
        int idx = base + i;
        if (idx < NN) {
            g_rowptr[idx] = run;
            g_cursor[idx] = run;
            run += g_cnt[idx];
        }
    }
    if (tid == 1023) g_rowptr[NN] = sm[1023];
}

__global__ void csr_fill_kernel(const int* __restrict__ src, const int* __restrict__ dst) {
    int e = blockIdx.x * blockDim.x + threadIdx.x;
    if (e >= NE) return;
    int d = dst[e];
    int s = src[e];
    int p = atomicAdd(&g_cursor[d], 1);
    g_col[p] = s;
    g_wgt[p] = g_is[s] * g_is[d];
}

// ---------------- aggregation: out[i] = sum_e w_e * h[src_e] + is^2 * h[i] ----
template <int H>
__global__ void agg_kernel(const float* __restrict__ h, float* __restrict__ out) {
    const int node = blockIdx.x * 4 + (threadIdx.x >> 5);
    if (node >= NN) return;
    const int lane = threadIdx.x & 31;
    constexpr int V = H / 128;  // float4 per lane

    float4 acc[V];
    float self = g_is[node];
    self = self * self;
    const float4* hrow = (const float4*)(h + (size_t)node * H);
#pragma unroll
    for (int v = 0; v < V; v++) {
        float4 t = hrow[lane + 32 * v];
        acc[v] = make_float4(t.x * self, t.y * self, t.z * self, t.w * self);
    }
    const int beg = g_rowptr[node];
    const int end = g_rowptr[node + 1];
    for (int p = beg; p < end; p++) {
        int s = g_col[p];
        float w = g_wgt[p];
        const float4* sr = (const float4*)(h + (size_t)s * H);
#pragma unroll
        for (int v = 0; v < V; v++) {
            float4 t = sr[lane + 32 * v];
            acc[v].x += w * t.x; acc[v].y += w * t.y;
            acc[v].z += w * t.z; acc[v].w += w * t.w;
        }
    }
    float4* orow = (float4*)(out + (size_t)node * H);
#pragma unroll
    for (int v = 0; v < V; v++) orow[lane + 32 * v] = acc[v];
}

// ---------------- fp32 tiled GEMM:  C[M,N] = act(A[M,K] @ W[K,N] + b) --------
// BM=BN=64, BK=16, 256 threads, 4x4 micro-tile per thread.
__global__ __launch_bounds__(256) void sgemm_kernel(
    const float* __restrict__ A, const float* __restrict__ W,
    const float* __restrict__ bias, float* __restrict__ C,
    int M, int K, int N, int relu) {
    __shared__ float As[16][68];   // [k][m], padded
    __shared__ float Bs[16][64];   // [k][n]

    const int tid = threadIdx.x;
    const int bm = blockIdx.y * 64;
    const int bn = blockIdx.x * 64;
    const int tx = tid & 15;       // n dir
    const int ty = tid >> 4;       // m dir

    const int a_r = tid >> 2;            // 0..63 row within tile
    const int a_c = (tid & 3) * 4;       // 0,4,8,12
    const int b_r = tid >> 4;            // 0..15
    const int b_c = (tid & 15) * 4;      // 0..60

    float acc[4][4] = {};

    for (int k0 = 0; k0 < K; k0 += 16) {
        float4 av = make_float4(0.f, 0.f, 0.f, 0.f);
        int gr = bm + a_r;
        if (gr < M) av = *(const float4*)(A + (size_t)gr * K + k0 + a_c);
        As[a_c + 0][a_r] = av.x;
        As[a_c + 1][a_r] = av.y;
        As[a_c + 2][a_r] = av.z;
        As[a_c + 3][a_r] = av.w;

        float4 bv = *(const float4*)(W + (size_t)(k0 + b_r) * N + bn + b_c);
        *(float4*)&Bs[b_r][b_c] = bv;
        __syncthreads();

#pragma unroll
        for (int k = 0; k < 16; k++) {
            float4 a4 = *(const float4*)&As[k][ty * 4];
            float4 b4 = *(const float4*)&Bs[k][tx * 4];
            float ar[4] = {a4.x, a4.y, a4.z, a4.w};
            float br[4] = {b4.x, b4.y, b4.z, b4.w};
#pragma unroll
            for (int i = 0; i < 4; i++)
#pragma unroll
                for (int j = 0; j < 4; j++) acc[i][j] += ar[i] * br[j];
        }
        __syncthreads();
    }

#pragma unroll
    for (int i = 0; i < 4; i++) {
        int row = bm + ty * 4 + i;
        if (row >= M) continue;
#pragma unroll
        for (int j = 0; j < 4; j++) {
            int colg = bn + tx * 4 + j;
            float v = acc[i][j] + bias[colg];
            if (relu) v = fmaxf(v, 0.f);
            C[(size_t)row * N + colg] = v;
        }
    }
}

// ---------------- final layer (512 -> 4) fused with graph pooling ------------
__global__ void final_kernel(const float* __restrict__ m2, const float* __restrict__ lw3,
                             const float* __restrict__ lb3, const int* __restrict__ batch) {
    const int node = blockIdx.x * 4 + (threadIdx.x >> 5);
    if (node >= NN) return;
    const int lane = threadIdx.x & 31;
    float a0 = 0.f, a1 = 0.f, a2 = 0.f, a3 = 0.f;
    const float* row = m2 + (size_t)node * 512;
    for (int k = lane; k < 512; k += 32) {
        float v = row[k];
        float4 w = *(const float4*)(lw3 + k * 4);
        a0 += v * w.x; a1 += v * w.y; a2 += v * w.z; a3 += v * w.w;
    }
#pragma unroll
    for (int off = 16; off > 0; off >>= 1) {
        a0 += __shfl_down_sync(0xffffffffu, a0, off);
        a1 += __shfl_down_sync(0xffffffffu, a1, off);
        a2 += __shfl_down_sync(0xffffffffu, a2, off);
        a3 += __shfl_down_sync(0xffffffffu, a3, off);
    }
    if (lane == 0) {
        int g = batch[node];
        atomicAdd(&g_gsum[g * 4 + 0], a0 + lb3[0]);
        atomicAdd(&g_gsum[g * 4 + 1], a1 + lb3[1]);
        atomicAdd(&g_gsum[g * 4 + 2], a2 + lb3[2]);
        atomicAdd(&g_gsum[g * 4 + 3], a3 + lb3[3]);
        atomicAdd(&g_gcnt[g], 1);
    }
}

__global__ void finalize_kernel(float* __restrict__ out) {
    int i = blockIdx.x * blockDim.x + threadIdx.x;
    if (i < NG * 4) {
        float c = fmaxf((float)g_gcnt[i >> 2], 1.f);
        out[i] = g_gsum[i] / c;
    }
}

// ---------------- launch ----------------
extern "C" void kernel_launch(void* const* d_in, const int* in_sizes, int n_in,
                              void* d_out, int out_size) {
    const float* x    = (const float*)d_in[0];
    const int*   ei   = (const int*)d_in[1];     // [2, NE]
    const int*   bat  = (const int*)d_in[2];
    const float* W1   = (const float*)d_in[3];
    const float* b1   = (const float*)d_in[4];
    const float* W2   = (const float*)d_in[5];
    const float* b2   = (const float*)d_in[6];
    const float* W3   = (const float*)d_in[7];
    const float* b3   = (const float*)d_in[8];
    const float* lw1  = (const float*)d_in[9];
    const float* lb1  = (const float*)d_in[10];
    const float* lw2  = (const float*)d_in[11];
    const float* lb2  = (const float*)d_in[12];
    const float* lw3  = (const float*)d_in[13];
    const float* lb3  = (const float*)d_in[14];
    float* out = (float*)d_out;

    const int* src = ei;
    const int* dst = ei + NE;

    float *bufA, *bufB, *bufC;
    cudaGetSymbolAddress((void**)&bufA, g_bufA);
    cudaGetSymbolAddress((void**)&bufB, g_bufB);
    cudaGetSymbolAddress((void**)&bufC, g_bufC);

    // ---- graph preprocessing ----
    zero_kernel<<<(NN + 255) / 256, 256>>>();
    hist_kernel<<<(NE + 255) / 256, 256>>>(dst);
    invsqrt_kernel<<<(NN + 255) / 256, 256>>>();
    scan_kernel<<<1, 1024>>>();
    csr_fill_kernel<<<(NE + 255) / 256, 256>>>(src, dst);

    const int aggBlocks = (NN + 3) / 4;

    // ---- layer 1: agg(x) @ W1 + b1, relu ----
    agg_kernel<128><<<aggBlocks, 128>>>(x, bufA);
    sgemm_kernel<<<dim3(128 / 64, (NN + 63) / 64), 256>>>(bufA, W1, b1, bufB, NN, 128, 128, 1);

    // ---- layer 2: agg(h1) @ W2 + b2, relu ----
    agg_kernel<128><<<aggBlocks, 128>>>(bufB, bufA);
    sgemm_kernel<<<dim3(256 / 64, (NN + 63) / 64), 256>>>(bufA, W2, b2, bufB, NN, 128, 256, 1);

    // ---- layer 3: agg(h2) @ W3 + b3 (no relu) ----
    agg_kernel<256><<<aggBlocks, 128>>>(bufB, bufA);
    sgemm_kernel<<<dim3(512 / 64, (NN + 63) / 64), 256>>>(bufA, W3, b3, bufB, NN, 256, 512, 0);

    // ---- MLP head ----
    sgemm_kernel<<<dim3(1024 / 64, (NN + 63) / 64), 256>>>(bufB, lw1, lb1, bufC, NN, 512, 1024, 1);
    sgemm_kernel<<<dim3(512 / 64, (NN + 63) / 64), 256>>>(bufC, lw2, lb2, bufA, NN, 1024, 512, 1);

    // ---- final layer + pooling ----
    final_kernel<<<aggBlocks, 128>>>(bufA, lw3, lb3, bat);
    finalize_kernel<<<(NG * 4 + 255) / 256, 256>>>(out);
}